// round 11
// baseline (speedup 1.0000x reference)
#include <cuda_runtime.h>
#include <cstdint>

#define B_ 256
#define K_ 16
#define H_ 512
#define D_ 64
#define NT 48           // 3 * K_ output columns per d

// Scratch (device globals: sanctioned alternative to cudaMalloc)
__device__ float g_xT[(size_t)D_ * B_ * H_];   // [d][b][h]  33.5 MB
__device__ float g_Vt[(size_t)D_ * NT * H_];   // [d][n][h]   6 MB  (n = m*16+k)
__device__ float g_part[B_ * D_];              // [b][d] partial results

// ---------------------------------------------------------------------------
// Kernel 1: transpose x[b][h][d] -> xT[d][b][h], V_m[k][h][d] -> Vt[d][m*16+k][h]
// (unchanged from R10 pass; 15.3us, issue-bound — next-round target)
// ---------------------------------------------------------------------------
__global__ void transpose_kernel(const float* __restrict__ x,
                                 const float* __restrict__ Va,
                                 const float* __restrict__ Vm,
                                 const float* __restrict__ Vs)
{
    __shared__ float tile[32][33];
    int tx = threadIdx.x, ty = threadIdx.y;
    int h0 = blockIdx.x * 32;
    int d0 = blockIdx.y * 32;
    int z  = blockIdx.z;

    const float* src;
    if (z < B_) {
        src = x + (size_t)z * H_ * D_;
    } else {
        int n = z - B_;
        int m = n >> 4, k = n & 15;
        const float* V = (m == 0) ? Va : ((m == 1) ? Vm : Vs);
        src = V + (size_t)k * H_ * D_;
    }

#pragma unroll
    for (int j = 0; j < 4; j++) {
        int r = ty + 8 * j;
        tile[r][tx] = src[(size_t)(h0 + r) * D_ + d0 + tx];
    }
    __syncthreads();
#pragma unroll
    for (int j = 0; j < 4; j++) {
        int r = ty + 8 * j;
        float v = tile[tx][r];
        if (z < B_)
            g_xT[((size_t)(d0 + r) * B_ + z) * H_ + h0 + tx] = v;
        else
            g_Vt[((size_t)(d0 + r) * NT + (z - B_)) * H_ + h0 + tx] = v;
    }
}

// ---------------------------------------------------------------------------
// Kernel 2: per-d GEMM, NOW M=64 b-tile (grid 4 x 64 = 256 blocks -> ~2
// blocks/SM = 4 warps/SMSP for latency hiding). Thread tile 2b x 6n.
// ---------------------------------------------------------------------------
__device__ __forceinline__ unsigned long long ffma2(unsigned long long a,
                                                    unsigned long long b,
                                                    unsigned long long c)
{
    unsigned long long d;
    asm("fma.rn.f32x2 %0, %1, %2, %3;" : "=l"(d) : "l"(a), "l"(b), "l"(c));
    return d;
}

#define MT 64                   // M tile (b rows per block)
#define HC 16
#define NCHUNK (H_ / HC)        // 32
#define XS_SZ (HC * MT)         // 1024 floats per buffer
#define VS_SZ (HC * 100)        // 50 float2-pairs * 16 h = 1600 floats per buffer
#define CS_STRIDE 49

__global__ __launch_bounds__(256)
void gemm_epi_kernel(const float* __restrict__ iv,
                     const float* __restrict__ ba,
                     const float* __restrict__ bm,
                     const float* __restrict__ bs)
{
    // smem: Xs[2][HC][64] ++ Vs2[2][HC][50][2] ++ bias[64]; Cs overlays front.
    __shared__ float sm[2 * XS_SZ + 2 * VS_SZ + 64];   // 21.2 KB
    float* bias = sm + 2 * XS_SZ + 2 * VS_SZ;

    int t  = threadIdx.x;
    int tx = t & 31;            // b-group (2 b's each: rows 2tx, 2tx+1)
    int ty = t >> 5;            // n-group (6 n's each, 8 groups)
    int d  = blockIdx.y;
    int bbase = blockIdx.x * MT;

    if (t < NT) {
        int m = t >> 4, k = t & 15;
        const float* bp = (m == 0) ? ba : ((m == 1) ? bm : bs);
        bias[t] = bp[k * D_ + d];
    }

    const float* xg = g_xT + ((size_t)d * B_ + bbase) * H_;
    const float* vg = g_Vt + (size_t)d * NT * H_;

    // loaders: x tile 64b x 16h = 256 float4 -> 1/thread; v tile 48n x 16h -> 3/thread
    int bl = t >> 2, hq = t & 3;          // bl 0..63, hq 0..3 (4-float h quad)
    int vn0 = t >> 4, vh0 = t & 15;

    float4 xr;
    float  vr0, vr1, vr2;
    xr  = *(const float4*)(xg + (size_t)bl * H_ + 4 * hq);
    vr0 = vg[(size_t)(vn0)      * H_ + vh0];
    vr1 = vg[(size_t)(vn0 + 16) * H_ + vh0];
    vr2 = vg[(size_t)(vn0 + 32) * H_ + vh0];

    unsigned long long acc[6];
#pragma unroll
    for (int j = 0; j < 6; j++) acc[j] = 0ull;

#pragma unroll 2
    for (int c = 0; c < NCHUNK; c++) {
        float* X  = sm + (c & 1) * XS_SZ;
        float* V2 = sm + 2 * XS_SZ + (c & 1) * VS_SZ;

        // STS x (transposed [h][b], XOR swizzle: banks covered exactly once)
        {
            int sw = bl ^ (hq << 3);
            X[(4 * hq + 0) * MT + sw] = xr.x;
            X[(4 * hq + 1) * MT + sw] = xr.y;
            X[(4 * hq + 2) * MT + sw] = xr.z;
            X[(4 * hq + 3) * MT + sw] = xr.w;
            *(float2*)(V2 + (vh0 * 50 + vn0)      * 2) = make_float2(vr0, vr0);
            *(float2*)(V2 + (vh0 * 50 + vn0 + 16) * 2) = make_float2(vr1, vr1);
            *(float2*)(V2 + (vh0 * 50 + vn0 + 32) * 2) = make_float2(vr2, vr2);
        }
        __syncthreads();

        // prefetch next chunk
        if (c + 1 < NCHUNK) {
            int h0 = (c + 1) * HC;
            xr  = *(const float4*)(xg + (size_t)bl * H_ + h0 + 4 * hq);
            vr0 = vg[(size_t)(vn0)      * H_ + h0 + vh0];
            vr1 = vg[(size_t)(vn0 + 16) * H_ + h0 + vh0];
            vr2 = vg[(size_t)(vn0 + 32) * H_ + h0 + vh0];
        }

#pragma unroll
        for (int h = 0; h < HC; h++) {
            int swz = (h >> 2) << 3;                 // matches store-side hq<<3
            unsigned long long x01 = __double_as_longlong(
                *(const double*)(X + h * MT + ((2 * tx) ^ swz)));
            const double2* vp = (const double2*)(V2 + (h * 50 + 6 * ty) * 2);
            double2 va = vp[0], vb = vp[1], vc = vp[2];   // warp-broadcast LDS
            unsigned long long vv[6] = {
                __double_as_longlong(va.x), __double_as_longlong(va.y),
                __double_as_longlong(vb.x), __double_as_longlong(vb.y),
                __double_as_longlong(vc.x), __double_as_longlong(vc.y)
            };
#pragma unroll
            for (int j = 0; j < 6; j++)
                acc[j] = ffma2(x01, vv[j], acc[j]);
        }
        // single sync per chunk: STS(c+2) reuses this buffer only after
        // SYNC(c+1), which post-dates every thread's compute(c).
    }

    __syncthreads();

    // stage C[64][48] to smem (stride 49; overlays tile buffers, below bias)
    float* Cs = sm;
#pragma unroll
    for (int j = 0; j < 6; j++) {
        int n = 6 * ty + j;
        unsigned long long a = acc[j];
        Cs[(2 * tx + 0) * CS_STRIDE + n] = __uint_as_float((unsigned)(a & 0xffffffffu));
        Cs[(2 * tx + 1) * CS_STRIDE + n] = __uint_as_float((unsigned)(a >> 32));
    }
    __syncthreads();

    // fused epilogue: per (b,d), lse_k(-0.5 z^2 + ea - ls) - lse_k(ea) - 0.5 log 2pi
    if (t < MT) {
        int b  = t;
        int bg = bbase + b;
        float y = iv[(size_t)bg * D_ + d];
        const float* Cb = Cs + b * CS_STRIDE;
        float gv[16], ev[16];
        float gm = -3.4e38f, em = -3.4e38f;
#pragma unroll
        for (int k = 0; k < 16; k++) {
            float ea = Cb[k]      + bias[k];
            float mu = Cb[16 + k] + bias[16 + k];
            float ls = Cb[32 + k] + bias[32 + k];
            ls = fminf(fmaxf(ls, -20.0f), 20.0f);
            float inv = __expf(-ls);           // 1/sigma without a division
            float z   = (y - mu) * inv;
            float g   = fmaf(-0.5f * z, z, ea - ls);
            gv[k] = g; ev[k] = ea;
            gm = fmaxf(gm, g); em = fmaxf(em, ea);
        }
        float sg = 0.0f, se = 0.0f;
#pragma unroll
        for (int k = 0; k < 16; k++) {
            sg += __expf(gv[k] - gm);
            se += __expf(ev[k] - em);
        }
        float val = (__logf(sg) + gm) - (__logf(se) + em) - 0.918938533204672741f;
        g_part[(size_t)bg * D_ + d] = val;
    }
}

// ---------------------------------------------------------------------------
// Kernel 3: deterministic reduction over d: out[b] = sum_d partial[b][d]
// ---------------------------------------------------------------------------
__global__ void reduce_kernel(float* __restrict__ out)
{
    int b = blockIdx.x;
    int t = threadIdx.x;                 // 64 threads = 2 warps
    float v = g_part[b * D_ + t];
#pragma unroll
    for (int o = 16; o > 0; o >>= 1)
        v += __shfl_down_sync(0xffffffffu, v, o);
    __shared__ float s[2];
    if ((t & 31) == 0) s[t >> 5] = v;
    __syncthreads();
    if (t == 0) out[b] = s[0] + s[1];
}

// ---------------------------------------------------------------------------
extern "C" void kernel_launch(void* const* d_in, const int* in_sizes, int n_in,
                              void* d_out, int out_size)
{
    const float* x  = (const float*)d_in[0];
    const float* iv = (const float*)d_in[1];
    const float* Va = (const float*)d_in[2];
    const float* Vm = (const float*)d_in[3];
    const float* Vs = (const float*)d_in[4];
    const float* ba = (const float*)d_in[5];
    const float* bm = (const float*)d_in[6];
    const float* bs = (const float*)d_in[7];

    transpose_kernel<<<dim3(16, 2, B_ + NT), dim3(32, 8)>>>(x, Va, Vm, Vs);
    // 4 b-tiles of 64 x 64 d = 256 blocks -> ~2 blocks/SM
    gemm_epi_kernel<<<dim3(4, D_), 256>>>(iv, ba, bm, bs);
    reduce_kernel<<<B_, D_>>>((float*)d_out);
}

// round 14
// speedup vs baseline: 1.3956x; 1.3956x over previous
#include <cuda_runtime.h>
#include <cstdint>

#define B_ 256
#define K_ 16
#define H_ 512
#define D_ 64
#define NT 48           // 3 * K_ output columns per d

__device__ float g_xT[(size_t)D_ * B_ * H_];   // [d][b][h]  33.5 MB
__device__ float g_Vt[(size_t)D_ * NT * H_];   // [d][n][h]   6 MB  (n = m*16+k)
__device__ float g_part[B_ * D_];              // [b][d] partial results

// ---------------------------------------------------------------------------
// Kernel 1: transpose, 4 z-slices per block (16 independent LDG->STS chains
// per thread; attacks the measured issue=55% latency limitation).
// ---------------------------------------------------------------------------
#define ZPB 4
__global__ void transpose_kernel(const float* __restrict__ x,
                                 const float* __restrict__ Va,
                                 const float* __restrict__ Vm,
                                 const float* __restrict__ Vs)
{
    __shared__ float tile[ZPB][32][33];
    int tx = threadIdx.x, ty = threadIdx.y;
    int h0 = blockIdx.x * 32;
    int d0 = blockIdx.y * 32;
    int z0 = blockIdx.z * ZPB;      // z-groups are homogeneous (256 and 48 both %4==0)

    const float* srcs[ZPB];
#pragma unroll
    for (int zz = 0; zz < ZPB; zz++) {
        int z = z0 + zz;
        if (z < B_) {
            srcs[zz] = x + (size_t)z * H_ * D_;
        } else {
            int n = z - B_;
            int m = n >> 4, k = n & 15;
            const float* V = (m == 0) ? Va : ((m == 1) ? Vm : Vs);
            srcs[zz] = V + (size_t)k * H_ * D_;
        }
    }

#pragma unroll
    for (int zz = 0; zz < ZPB; zz++)
#pragma unroll
        for (int j = 0; j < 4; j++) {
            int r = ty + 8 * j;
            tile[zz][r][tx] = srcs[zz][(size_t)(h0 + r) * D_ + d0 + tx];
        }
    __syncthreads();
#pragma unroll
    for (int zz = 0; zz < ZPB; zz++) {
        int z = z0 + zz;
#pragma unroll
        for (int j = 0; j < 4; j++) {
            int r = ty + 8 * j;
            float v = tile[zz][tx][r];
            if (z < B_)
                g_xT[((size_t)(d0 + r) * B_ + z) * H_ + h0 + tx] = v;
            else
                g_Vt[((size_t)(d0 + r) * NT + (z - B_)) * H_ + h0 + tx] = v;
        }
    }
}

// ---------------------------------------------------------------------------
// Kernel 2: per-d GEMM, MT=128 (R10 config: 128 blocks, balanced 1/SM),
// distance-2 register prefetch to cover ~1.5-2K-cyc LDG latency (R11 lesson:
// the binding constraint was exposed prefetch latency, not warp count).
// ---------------------------------------------------------------------------
__device__ __forceinline__ unsigned long long ffma2(unsigned long long a,
                                                    unsigned long long b,
                                                    unsigned long long c)
{
    unsigned long long d;
    asm("fma.rn.f32x2 %0, %1, %2, %3;" : "=l"(d) : "l"(a), "l"(b), "l"(c));
    return d;
}

#define HC 16
#define NCHUNK (H_ / HC)        // 32 (even; loop unrolled by 2)
#define XS_SZ (HC * 128)        // 2048 floats per buffer
#define VS_SZ (HC * 100)        // 1600 floats per buffer
#define CS_STRIDE 49

__global__ __launch_bounds__(256, 1)
void gemm_epi_kernel(const float* __restrict__ iv,
                     const float* __restrict__ ba,
                     const float* __restrict__ bm,
                     const float* __restrict__ bs)
{
    __shared__ float sm[2 * XS_SZ + 2 * VS_SZ + 64];   // 29.4 KB
    float* bias = sm + 2 * XS_SZ + 2 * VS_SZ;

    int t  = threadIdx.x;
    int tx = t & 31;            // b-group (4 b's each)
    int ty = t >> 5;            // n-group (6 n's each)
    int d  = blockIdx.y;
    int bbase = blockIdx.x * 128;

    if (t < NT) {
        int m = t >> 4, k = t & 15;
        const float* bp = (m == 0) ? ba : ((m == 1) ? bm : bs);
        bias[t] = bp[k * D_ + d];
    }

    const float* xg = g_xT + ((size_t)d * B_ + bbase) * H_;
    const float* vg = g_Vt + (size_t)d * NT * H_;

    int bl0 = t >> 2, hq0 = t & 3;
    int bl1 = bl0 + 64;                 // second x float4 (hq identical)
    int vn0 = t >> 4, vh0 = t & 15;

    // two in-flight register sets (A: even chunks, B: odd chunks)
    float4 xrA0, xrA1, xrB0, xrB1;
    float  vrA0, vrA1, vrA2, vrB0, vrB1, vrB2;

    auto loadA = [&](int h0) {
        xrA0 = *(const float4*)(xg + (size_t)bl0 * H_ + h0 + 4 * hq0);
        xrA1 = *(const float4*)(xg + (size_t)bl1 * H_ + h0 + 4 * hq0);
        vrA0 = vg[(size_t)(vn0)      * H_ + h0 + vh0];
        vrA1 = vg[(size_t)(vn0 + 16) * H_ + h0 + vh0];
        vrA2 = vg[(size_t)(vn0 + 32) * H_ + h0 + vh0];
    };
    auto loadB = [&](int h0) {
        xrB0 = *(const float4*)(xg + (size_t)bl0 * H_ + h0 + 4 * hq0);
        xrB1 = *(const float4*)(xg + (size_t)bl1 * H_ + h0 + 4 * hq0);
        vrB0 = vg[(size_t)(vn0)      * H_ + h0 + vh0];
        vrB1 = vg[(size_t)(vn0 + 16) * H_ + h0 + vh0];
        vrB2 = vg[(size_t)(vn0 + 32) * H_ + h0 + vh0];
    };
    auto doSTS = [&](float* X, float* V2, float4 x0, float4 x1,
                     float v0, float v1, float v2) {
        int sw = bl0 ^ (hq0 << 3);
        X[(4 * hq0 + 0) * 128 + sw] = x0.x;
        X[(4 * hq0 + 1) * 128 + sw] = x0.y;
        X[(4 * hq0 + 2) * 128 + sw] = x0.z;
        X[(4 * hq0 + 3) * 128 + sw] = x0.w;
        int sw1 = bl1 ^ (hq0 << 3);
        X[(4 * hq0 + 0) * 128 + sw1] = x1.x;
        X[(4 * hq0 + 1) * 128 + sw1] = x1.y;
        X[(4 * hq0 + 2) * 128 + sw1] = x1.z;
        X[(4 * hq0 + 3) * 128 + sw1] = x1.w;
        *(float2*)(V2 + (vh0 * 50 + vn0)      * 2) = make_float2(v0, v0);
        *(float2*)(V2 + (vh0 * 50 + vn0 + 16) * 2) = make_float2(v1, v1);
        *(float2*)(V2 + (vh0 * 50 + vn0 + 32) * 2) = make_float2(v2, v2);
    };

    unsigned long long acc0[6], acc1[6];
#pragma unroll
    for (int j = 0; j < 6; j++) { acc0[j] = 0ull; acc1[j] = 0ull; }

    auto compute = [&](const float* X, const float* V2) {
#pragma unroll
        for (int h = 0; h < HC; h++) {
            int swz = (h >> 2) << 3;
            double2 xd = *(const double2*)(X + h * 128 + ((4 * tx) ^ swz));
            unsigned long long x01 = __double_as_longlong(xd.x);
            unsigned long long x23 = __double_as_longlong(xd.y);
            const double2* vp = (const double2*)(V2 + (h * 50 + 6 * ty) * 2);
            double2 va = vp[0], vb = vp[1], vc = vp[2];
            unsigned long long vv[6] = {
                __double_as_longlong(va.x), __double_as_longlong(va.y),
                __double_as_longlong(vb.x), __double_as_longlong(vb.y),
                __double_as_longlong(vc.x), __double_as_longlong(vc.y)
            };
#pragma unroll
            for (int j = 0; j < 6; j++) {
                acc0[j] = ffma2(x01, vv[j], acc0[j]);
                acc1[j] = ffma2(x23, vv[j], acc1[j]);
            }
        }
    };

    loadA(0);
    loadB(HC);

#pragma unroll 1
    for (int c = 0; c < NCHUNK; c += 2) {
        // even chunk c: buffer 0, set A
        doSTS(sm, sm + 2 * XS_SZ, xrA0, xrA1, vrA0, vrA1, vrA2);
        __syncthreads();
        if (c + 2 < NCHUNK) loadA((c + 2) * HC);   // distance-2 prefetch
        compute(sm, sm + 2 * XS_SZ);

        // odd chunk c+1: buffer 1, set B
        doSTS(sm + XS_SZ, sm + 2 * XS_SZ + VS_SZ, xrB0, xrB1, vrB0, vrB1, vrB2);
        __syncthreads();
        if (c + 3 < NCHUNK) loadB((c + 3) * HC);
        compute(sm + XS_SZ, sm + 2 * XS_SZ + VS_SZ);
        // buffer reuse safe: STS(c+2) into buffer 0 happens only after
        // sync(c+1), which post-dates every thread's compute(c).
    }

    __syncthreads();

    // stage C[128][48] to smem (stride 49; overlays tile buffers, below bias)
    float* Cs = sm;
#pragma unroll
    for (int j = 0; j < 6; j++) {
        int n = 6 * ty + j;
        unsigned long long a0 = acc0[j], a1 = acc1[j];
        Cs[(4 * tx + 0) * CS_STRIDE + n] = __uint_as_float((unsigned)(a0 & 0xffffffffu));
        Cs[(4 * tx + 1) * CS_STRIDE + n] = __uint_as_float((unsigned)(a0 >> 32));
        Cs[(4 * tx + 2) * CS_STRIDE + n] = __uint_as_float((unsigned)(a1 & 0xffffffffu));
        Cs[(4 * tx + 3) * CS_STRIDE + n] = __uint_as_float((unsigned)(a1 >> 32));
    }
    __syncthreads();

    // fused epilogue: per (b,d), lse_k(-0.5 z^2 + ea - ls) - lse_k(ea) - 0.5 log 2pi
    if (t < 128) {
        int b  = t;
        int bg = bbase + b;
        float y = iv[(size_t)bg * D_ + d];
        const float* Cb = Cs + b * CS_STRIDE;
        float gv[16], ev[16];
        float gm = -3.4e38f, em = -3.4e38f;
#pragma unroll
        for (int k = 0; k < 16; k++) {
            float ea = Cb[k]      + bias[k];
            float mu = Cb[16 + k] + bias[16 + k];
            float ls = Cb[32 + k] + bias[32 + k];
            ls = fminf(fmaxf(ls, -20.0f), 20.0f);
            float inv = __expf(-ls);
            float z   = (y - mu) * inv;
            float g   = fmaf(-0.5f * z, z, ea - ls);
            gv[k] = g; ev[k] = ea;
            gm = fmaxf(gm, g); em = fmaxf(em, ea);
        }
        float sg = 0.0f, se = 0.0f;
#pragma unroll
        for (int k = 0; k < 16; k++) {
            sg += __expf(gv[k] - gm);
            se += __expf(ev[k] - em);
        }
        float val = (__logf(sg) + gm) - (__logf(se) + em) - 0.918938533204672741f;
        g_part[(size_t)bg * D_ + d] = val;
    }
}

// ---------------------------------------------------------------------------
// Kernel 3: deterministic reduction over d: out[b] = sum_d partial[b][d]
// ---------------------------------------------------------------------------
__global__ void reduce_kernel(float* __restrict__ out)
{
    int b = blockIdx.x;
    int t = threadIdx.x;                 // 64 threads = 2 warps
    float v = g_part[b * D_ + t];
#pragma unroll
    for (int o = 16; o > 0; o >>= 1)
        v += __shfl_down_sync(0xffffffffu, v, o);
    __shared__ float s[2];
    if ((t & 31) == 0) s[t >> 5] = v;
    __syncthreads();
    if (t == 0) out[b] = s[0] + s[1];
}

// ---------------------------------------------------------------------------
extern "C" void kernel_launch(void* const* d_in, const int* in_sizes, int n_in,
                              void* d_out, int out_size)
{
    const float* x  = (const float*)d_in[0];
    const float* iv = (const float*)d_in[1];
    const float* Va = (const float*)d_in[2];
    const float* Vm = (const float*)d_in[3];
    const float* Vs = (const float*)d_in[4];
    const float* ba = (const float*)d_in[5];
    const float* bm = (const float*)d_in[6];
    const float* bs = (const float*)d_in[7];

    transpose_kernel<<<dim3(16, 2, (B_ + NT) / ZPB), dim3(32, 8)>>>(x, Va, Vm, Vs);
    gemm_epi_kernel<<<dim3(2, D_), 256>>>(iv, ba, bm, bs);
    reduce_kernel<<<B_, D_>>>((float*)d_out);
}